// round 15
// baseline (speedup 1.0000x reference)
#include <cuda_runtime.h>
#include <cuda_bf16.h>
#include <cstdint>

#define NNODE 4096
#define INF   256
#define OUTF  32
#define NH    8
#define NEG_SLOPE 0.2f
#define DEGCAP 240

__device__ float          g_Wh[NH * NNODE * OUTF];   // [h][n][f], 4 MB
__device__ float          g_esrc[NH * NNODE];
__device__ float          g_edst[NH * NNODE];
__device__ int            g_deg[NNODE];
__device__ unsigned short g_adjn[NNODE][DEGCAP];
__device__ int            g_kind;                    // 0 = u8, 1 = 32-bit

__device__ __forceinline__ uint32_t smem_u32(const void* p) {
    uint32_t a;
    asm("{ .reg .u64 t; cvta.to.shared.u64 t, %1; cvt.u32.u64 %0, t; }"
        : "=r"(a) : "l"(p));
    return a;
}
#define LDSM4(r0, r1, r2, r3, addr)                                          \
    asm volatile("ldmatrix.sync.aligned.m8n8.x4.shared.b16 {%0,%1,%2,%3}, [%4];" \
                 : "=r"(r0), "=r"(r1), "=r"(r2), "=r"(r3) : "r"(addr))
#define MMA_BF16(c, a, b0, b1)                                               \
    asm volatile("mma.sync.aligned.m16n8k16.row.col.f32.bf16.bf16.f32 "      \
                 "{%0,%1,%2,%3}, {%4,%5,%6,%7}, {%8,%9}, {%0,%1,%2,%3};"     \
                 : "+f"((c)[0]), "+f"((c)[1]), "+f"((c)[2]), "+f"((c)[3])    \
                 : "r"((a)[0]), "r"((a)[1]), "r"((a)[2]), "r"((a)[3]),       \
                   "r"(b0), "r"(b1))

__device__ __forceinline__ uint32_t pack2(float lo, float hi) {
    uint32_t r;
    asm("cvt.rn.bf16x2.f32 %0, %1, %2;" : "=r"(r) : "f"(hi), "f"(lo));
    return r;
}

// smem layout: pitch 80 B per row (40 bf16); A 32 rows, B 64 cols
#define PITCH 80
#define SM_AHI 0
#define SM_ALO 2560
#define SM_BHI 5120
#define SM_BLO 10240

// ---------------------------------------------------------------------------
// gemm_tc: bf16 split-GEMM via mma.sync.  Wh[n, h*32+f] = sum_i x[n,i]*W[h,i,f]
// 512 CTAs x 128 thr; CTA tile 32M x 64N; warp tile 16x32 (one head/warp).
// D += Ahi*Bhi + Ahi*Blo + Alo*Bhi  (fp32 accum; rel err ~1e-5).
// Fused: logit epilogue + adjacency dtype detect (block 0).
// ---------------------------------------------------------------------------
__global__ void __launch_bounds__(128) gemm_tc_kernel(
    const float* __restrict__ x, const float* __restrict__ W,
    const float* __restrict__ a_src, const float* __restrict__ a_dst,
    const void* __restrict__ adjv) {
    __shared__ alignas(128) unsigned char sm[15360];
    __shared__ int s_flag;

    const int t    = threadIdx.x;
    const int bx   = blockIdx.x;
    const int w    = t >> 5;
    const int lane = t & 31;
    const uint32_t base = smem_u32(sm);

    // --- dtype detect (block 0): 16 KB sample, byte pos 1 mod 4
    if (bx == 0) {
        if (t == 0) s_flag = 0;
        __syncthreads();
        unsigned f = 0;
        const uint4* s4 = (const uint4*)adjv;
#pragma unroll
        for (int q = 0; q < 8; q++) {
            uint4 v = s4[t + q * 128];
            f |= ((v.x >> 8) & 0xFFu) | ((v.y >> 8) & 0xFFu)
               | ((v.z >> 8) & 0xFFu) | ((v.w >> 8) & 0xFFu);
        }
#pragma unroll
        for (int o = 16; o; o >>= 1)
            f |= __shfl_xor_sync(0xffffffffu, f, o);
        if (lane == 0 && f) atomicOr(&s_flag, 1);
        __syncthreads();
        if (t == 0) g_kind = s_flag ? 0 : 1;
    }

    const int row0 = (bx >> 2) * 32;    // 128 row tiles
    const int hb   = (bx & 3) * 2;      // heads hb, hb+1
    const int wm   = (w & 1) * 16;      // warp row offset (0 / 16)
    const int wn   = (w >> 1) * 32;     // warp col offset (0 / 32) = head sel

    float acc[4][4];                    // [nf][c0..c3]
#pragma unroll
    for (int b = 0; b < 4; b++)
#pragma unroll
        for (int c = 0; c < 4; c++) acc[b][c] = 0.f;

    // lane-constant ldmatrix addressing
    const uint32_t a_m  = (uint32_t)(wm + ((lane >> 3) & 1) * 8 + (lane & 7));
    const uint32_t a_k8 = (uint32_t)((lane >> 4) * 8);
    const uint32_t b_n  = (uint32_t)(wn + ((lane >> 4) & 1) * 8 + (lane & 7));
    const uint32_t b_k8 = (uint32_t)(((lane >> 3) & 1) * 8);

#pragma unroll 1
    for (int c = 0; c < 8; c++) {
        const int k0 = c * 32;
        // global loads (issued before waiting on smem reuse)
        float4 xr[2];
#pragma unroll
        for (int j = 0; j < 2; j++) {
            int idx = t + 128 * j;                        // 0..255
            xr[j] = *(const float4*)(x + (size_t)(row0 + (idx >> 3)) * INF + k0 + (idx & 7) * 4);
        }
        float wv[16];
#pragma unroll
        for (int j = 0; j < 16; j++) {
            int idx = t + 128 * j;                        // 0..2047
            int n = idx & 63, k = idx >> 6;
            int h = hb + (n >> 5), f = n & 31;
            wv[j] = W[((size_t)h * INF + k0 + k) * OUTF + f];
        }
        if (c > 0) __syncthreads();       // prior MMAs done with smem

        // stage A hi/lo
#pragma unroll
        for (int j = 0; j < 2; j++) {
            int idx = t + 128 * j;
            int row = idx >> 3, kq = idx & 7;
            float4 v = xr[j];
            __nv_bfloat16 h0 = __float2bfloat16(v.x), h1 = __float2bfloat16(v.y);
            __nv_bfloat16 h2 = __float2bfloat16(v.z), h3 = __float2bfloat16(v.w);
            uint2 hp;
            hp.x = pack2(__bfloat162float(h0), __bfloat162float(h1));
            hp.y = pack2(__bfloat162float(h2), __bfloat162float(h3));
            uint2 lp;
            lp.x = pack2(v.x - __bfloat162float(h0), v.y - __bfloat162float(h1));
            lp.y = pack2(v.z - __bfloat162float(h2), v.w - __bfloat162float(h3));
            *(uint2*)(sm + SM_AHI + row * PITCH + kq * 8) = hp;
            *(uint2*)(sm + SM_ALO + row * PITCH + kq * 8) = lp;
        }
        // stage B hi/lo
#pragma unroll
        for (int j = 0; j < 16; j++) {
            int idx = t + 128 * j;
            int n = idx & 63, k = idx >> 6;
            float v = wv[j];
            __nv_bfloat16 h = __float2bfloat16(v);
            float hf = __bfloat162float(h);
            __nv_bfloat16 l = __float2bfloat16(v - hf);
            *(unsigned short*)(sm + SM_BHI + n * PITCH + k * 2) = __bfloat16_as_ushort(h);
            *(unsigned short*)(sm + SM_BLO + n * PITCH + k * 2) = __bfloat16_as_ushort(l);
        }
        __syncthreads();

        // fragments + MMA
#pragma unroll
        for (int ks = 0; ks < 32; ks += 16) {
            uint32_t ah[4], al[4], bh[4][2], bl[4][2];
            {
                uint32_t addr = base + SM_AHI + a_m * PITCH + (ks + a_k8) * 2;
                LDSM4(ah[0], ah[1], ah[2], ah[3], addr);
                LDSM4(al[0], al[1], al[2], al[3], addr + (SM_ALO - SM_AHI));
            }
#pragma unroll
            for (int np = 0; np < 2; np++) {
                uint32_t addr = base + SM_BHI + (b_n + np * 16) * PITCH + (ks + b_k8) * 2;
                uint32_t r0, r1, r2, r3;
                LDSM4(r0, r1, r2, r3, addr);
                bh[np * 2][0] = r0; bh[np * 2][1] = r1;
                bh[np * 2 + 1][0] = r2; bh[np * 2 + 1][1] = r3;
                LDSM4(r0, r1, r2, r3, addr + (SM_BLO - SM_BHI));
                bl[np * 2][0] = r0; bl[np * 2][1] = r1;
                bl[np * 2 + 1][0] = r2; bl[np * 2 + 1][1] = r3;
            }
#pragma unroll
            for (int nf = 0; nf < 4; nf++) {
                MMA_BF16(acc[nf], ah, bh[nf][0], bh[nf][1]);
                MMA_BF16(acc[nf], ah, bl[nf][0], bl[nf][1]);
                MMA_BF16(acc[nf], al, bh[nf][0], bh[nf][1]);
            }
        }
    }

    // epilogue: store Wh + fused logits (one head per warp)
    const int h  = hb + (w >> 1);
    const int g  = lane >> 2;
    const int tg = lane & 3;
    float asv[4][2], adv[4][2];
#pragma unroll
    for (int nf = 0; nf < 4; nf++) {
        asv[nf][0] = a_src[h * OUTF + nf * 8 + tg * 2];
        asv[nf][1] = a_src[h * OUTF + nf * 8 + tg * 2 + 1];
        adv[nf][0] = a_dst[h * OUTF + nf * 8 + tg * 2];
        adv[nf][1] = a_dst[h * OUTF + nf * 8 + tg * 2 + 1];
    }
    {
        const int mrow = row0 + wm;
        float s0 = 0.f, d0 = 0.f, s1 = 0.f, d1 = 0.f;
#pragma unroll
        for (int nf = 0; nf < 4; nf++) {
            float c0 = acc[nf][0], c1 = acc[nf][1];
            float c2 = acc[nf][2], c3 = acc[nf][3];
            const int f = nf * 8 + tg * 2;
            float2 vlo; vlo.x = c0; vlo.y = c1;
            float2 vhi; vhi.x = c2; vhi.y = c3;
            *(float2*)(g_Wh + ((size_t)(h << 12) + mrow + g) * OUTF + f)     = vlo;
            *(float2*)(g_Wh + ((size_t)(h << 12) + mrow + 8 + g) * OUTF + f) = vhi;
            s0 += c0 * asv[nf][0] + c1 * asv[nf][1];
            d0 += c0 * adv[nf][0] + c1 * adv[nf][1];
            s1 += c2 * asv[nf][0] + c3 * asv[nf][1];
            d1 += c2 * adv[nf][0] + c3 * adv[nf][1];
        }
#pragma unroll
        for (int o = 1; o < 4; o <<= 1) {
            s0 += __shfl_xor_sync(0xffffffffu, s0, o);
            d0 += __shfl_xor_sync(0xffffffffu, d0, o);
            s1 += __shfl_xor_sync(0xffffffffu, s1, o);
            d1 += __shfl_xor_sync(0xffffffffu, d1, o);
        }
        if (tg == 0) {
            g_esrc[(h << 12) + mrow + g]     = s0;
            g_edst[(h << 12) + mrow + g]     = d0;
            g_esrc[(h << 12) + mrow + 8 + g] = s1;
            g_edst[(h << 12) + mrow + 8 + g] = d1;
        }
    }
}

__device__ __forceinline__ unsigned nib4(unsigned m) {
    return (((m & 0x01010101u) * 0x01020408u) >> 24) & 0xFu;
}

// ---------------------------------------------------------------------------
// scan: 1024 blocks x 128 thr, warp per row, prefetched stream (reads g_kind).
// ---------------------------------------------------------------------------
__global__ void __launch_bounds__(128) scan_kernel(const void* __restrict__ adjv) {
    const int t    = threadIdx.x;
    const int lane = t & 31;
    const int w    = t >> 5;
    const int r    = blockIdx.x * 4 + w;
    const int kind = g_kind;

    int base = 0;
    if (kind == 0) {
        const uint4* rp = (const uint4*)((const unsigned char*)adjv + (size_t)r * NNODE);
        uint4 cur = rp[lane];
        for (int it = 0; it < 8; it++) {
            uint4 nxt;
            if (it < 7) nxt = rp[(it + 1) * 32 + lane];
            unsigned m16 =  nib4(__vcmpne4(cur.x, 0u))
                         | (nib4(__vcmpne4(cur.y, 0u)) << 4)
                         | (nib4(__vcmpne4(cur.z, 0u)) << 8)
                         | (nib4(__vcmpne4(cur.w, 0u)) << 12);
            const int c0 = (it << 9) + (lane << 4);
            if ((unsigned)(r - c0) < 16u) m16 |= 1u << (r - c0);
            int cnt = __popc(m16), incl = cnt;
#pragma unroll
            for (int o = 1; o < 32; o <<= 1) {
                int v = __shfl_up_sync(0xffffffffu, incl, o);
                if (lane >= o) incl += v;
            }
            int pos = base + (incl - cnt);
            int tot = __shfl_sync(0xffffffffu, incl, 31);
            while (m16) {
                int bi = __ffs(m16) - 1;
                m16 &= m16 - 1;
                if (pos < DEGCAP) g_adjn[r][pos] = (unsigned short)(c0 + bi);
                pos++;
            }
            base += tot;
            cur = nxt;
        }
    } else {
        const uint4* rp = (const uint4*)((const unsigned char*)adjv + ((size_t)r * NNODE << 2));
        uint4 cur[4];
#pragma unroll
        for (int q = 0; q < 4; q++) cur[q] = rp[lane * 4 + q];
        for (int it = 0; it < 8; it++) {
            uint4 nxt[4];
            if (it < 7) {
#pragma unroll
                for (int q = 0; q < 4; q++)
                    nxt[q] = rp[(it + 1) * 128 + lane * 4 + q];
            }
            unsigned m16 = 0;
#pragma unroll
            for (int q = 0; q < 4; q++) {
                m16 |= (unsigned)(cur[q].x != 0) << (q * 4 + 0);
                m16 |= (unsigned)(cur[q].y != 0) << (q * 4 + 1);
                m16 |= (unsigned)(cur[q].z != 0) << (q * 4 + 2);
                m16 |= (unsigned)(cur[q].w != 0) << (q * 4 + 3);
            }
            const int c0 = (it << 9) + (lane << 4);
            if ((unsigned)(r - c0) < 16u) m16 |= 1u << (r - c0);
            int cnt = __popc(m16), incl = cnt;
#pragma unroll
            for (int o = 1; o < 32; o <<= 1) {
                int v = __shfl_up_sync(0xffffffffu, incl, o);
                if (lane >= o) incl += v;
            }
            int pos = base + (incl - cnt);
            int tot = __shfl_sync(0xffffffffu, incl, 31);
            while (m16) {
                int bi = __ffs(m16) - 1;
                m16 &= m16 - 1;
                if (pos < DEGCAP) g_adjn[r][pos] = (unsigned short)(c0 + bi);
                pos++;
            }
            base += tot;
#pragma unroll
            for (int q = 0; q < 4; q++) cur[q] = nxt[q];
        }
    }
    if (lane == 31) g_deg[r] = (base > DEGCAP) ? DEGCAP : base;
}

// ---------------------------------------------------------------------------
// agg: warp per (node, head); edge-parallel alpha, shfl-broadcast gather.
// ---------------------------------------------------------------------------
__global__ void __launch_bounds__(256) agg_kernel(
    const float* __restrict__ bias, float* __restrict__ out) {
    const int i    = blockIdx.x;
    const int t    = threadIdx.x;
    const int w    = t >> 5;
    const int lane = t & 31;

    const int    deg = g_deg[i];
    const float  es  = g_esrc[(w << 12) + i];
    const float* ed  = g_edst + (w << 12);
    const float* whb = g_Wh + (((size_t)w << 12) * OUTF) + lane;

    float acc = 0.f, ssum = 0.f;
    for (int c0 = 0; c0 < deg; c0 += 32) {
        const int k = c0 + lane;
        int   j = 0;
        float p = 0.f;
        if (k < deg) {
            j = (int)g_adjn[i][k];
            float e = es + __ldg(&ed[j]);
            e = (e >= 0.f) ? e : NEG_SLOPE * e;
            p = __expf(e);
        }
        ssum += p;
        const int m = (deg - c0 < 32) ? (deg - c0) : 32;
        int kk = 0;
        for (; kk + 2 <= m; kk += 2) {
            int   ja = __shfl_sync(0xffffffffu, j, kk);
            float pa = __shfl_sync(0xffffffffu, p, kk);
            int   jb = __shfl_sync(0xffffffffu, j, kk + 1);
            float pb = __shfl_sync(0xffffffffu, p, kk + 1);
            float wa = whb[(size_t)ja * OUTF];
            float wb = whb[(size_t)jb * OUTF];
            acc = fmaf(pa, wa, acc);
            acc = fmaf(pb, wb, acc);
        }
        if (kk < m) {
            int   ja = __shfl_sync(0xffffffffu, j, kk);
            float pa = __shfl_sync(0xffffffffu, p, kk);
            acc = fmaf(pa, whb[(size_t)ja * OUTF], acc);
        }
    }
#pragma unroll
    for (int o = 16; o; o >>= 1)
        ssum += __shfl_xor_sync(0xffffffffu, ssum, o);

    out[(size_t)i * (NH * OUTF) + w * OUTF + lane] = acc / ssum + bias[w * OUTF + lane];
}

// ---------------------------------------------------------------------------
extern "C" void kernel_launch(void* const* d_in, const int* in_sizes, int n_in,
                              void* d_out, int out_size) {
    const float* x     = (const float*)d_in[0];
    const void*  adj   = d_in[1];
    const float* W     = (const float*)d_in[2];
    const float* a_src = (const float*)d_in[3];
    const float* a_dst = (const float*)d_in[4];
    const float* bias  = (const float*)d_in[5];
    float*       out   = (float*)d_out;

    gemm_tc_kernel<<<512, 128>>>(x, W, a_src, a_dst, adj);  // writes g_kind (block 0)
    scan_kernel<<<NNODE / 4, 128>>>(adj);                   // reads g_kind
    agg_kernel<<<NNODE, 256>>>(bias, out);
}

// round 16
// speedup vs baseline: 1.2128x; 1.2128x over previous
#include <cuda_runtime.h>
#include <cuda_bf16.h>
#include <cstdint>

#define NNODE 4096
#define INF   256
#define OUTF  32
#define NH    8
#define NEG_SLOPE 0.2f
#define DEGCAP 240

__device__ float          g_Wh[NH * NNODE * OUTF];   // [h][n][f], 4 MB
__device__ float          g_esrc[NH * NNODE];
__device__ float          g_edst[NH * NNODE];
__device__ int            g_deg[NNODE];
__device__ unsigned short g_adjn[NNODE][DEGCAP];
__device__ int            g_kind;                    // 0 = u8, 1 = 32-bit

__device__ __forceinline__ uint32_t smem_u32(const void* p) {
    uint32_t a;
    asm("{ .reg .u64 t; cvta.to.shared.u64 t, %1; cvt.u32.u64 %0, t; }"
        : "=r"(a) : "l"(p));
    return a;
}
#define LDSM4(r0, r1, r2, r3, addr)                                          \
    asm volatile("ldmatrix.sync.aligned.m8n8.x4.shared.b16 {%0,%1,%2,%3}, [%4];" \
                 : "=r"(r0), "=r"(r1), "=r"(r2), "=r"(r3) : "r"(addr))
#define MMA_BF16(c, a, b0, b1)                                               \
    asm volatile("mma.sync.aligned.m16n8k16.row.col.f32.bf16.bf16.f32 "      \
                 "{%0,%1,%2,%3}, {%4,%5,%6,%7}, {%8,%9}, {%0,%1,%2,%3};"     \
                 : "+f"((c)[0]), "+f"((c)[1]), "+f"((c)[2]), "+f"((c)[3])    \
                 : "r"((a)[0]), "r"((a)[1]), "r"((a)[2]), "r"((a)[3]),       \
                   "r"(b0), "r"(b1))

__device__ __forceinline__ uint32_t pack2(float lo, float hi) {
    uint32_t r;
    asm("cvt.rn.bf16x2.f32 %0, %1, %2;" : "=r"(r) : "f"(hi), "f"(lo));
    return r;
}

// smem layout per buffer: pitch 80 B per row (40 bf16)
#define PITCH   80
#define SM_AHI  0
#define SM_ALO  10240
#define SM_BHI  20480
#define SM_BLO  25600
#define BUF_SZ  30720
#define DSMEM_BYTES (2 * BUF_SZ)

// ---------------------------------------------------------------------------
// gemm_tc: bf16 split-GEMM via mma.sync, DOUBLE-BUFFERED smem pipeline.
// Wh[n, h*32+f] = sum_i x[n,i]*W[h,i,f]
// 128 CTAs x 256 thr; CTA tile 128M x 64N; warp tile 32x32 (one head/warp).
// D += Ahi*Bhi + Ahi*Blo + Alo*Bhi  (fp32 accum; rel err ~1e-5).
// Fused: logit epilogue + adjacency dtype detect (block 0).
// ---------------------------------------------------------------------------
__global__ void __launch_bounds__(256) gemm_tc_kernel(
    const float* __restrict__ x, const float* __restrict__ W,
    const float* __restrict__ a_src, const float* __restrict__ a_dst,
    const void* __restrict__ adjv) {
    extern __shared__ unsigned char sm[];
    __shared__ int s_flag;

    const int t    = threadIdx.x;
    const int bx   = blockIdx.x;
    const int w    = t >> 5;
    const int lane = t & 31;
    const uint32_t base = smem_u32(sm);

    // --- dtype detect (block 0): 16 KB sample, byte pos 1 mod 4
    if (bx == 0) {
        if (t == 0) s_flag = 0;
        __syncthreads();
        unsigned f = 0;
        const uint4* s4 = (const uint4*)adjv;
#pragma unroll
        for (int q = 0; q < 4; q++) {
            uint4 v = s4[t + q * 256];
            f |= ((v.x >> 8) & 0xFFu) | ((v.y >> 8) & 0xFFu)
               | ((v.z >> 8) & 0xFFu) | ((v.w >> 8) & 0xFFu);
        }
#pragma unroll
        for (int o = 16; o; o >>= 1)
            f |= __shfl_xor_sync(0xffffffffu, f, o);
        if (lane == 0 && f) atomicOr(&s_flag, 1);
        __syncthreads();
        if (t == 0) g_kind = s_flag ? 0 : 1;
    }

    const int row0 = (bx >> 2) * 128;   // 32 row tiles
    const int hb   = (bx & 3) * 2;      // heads hb, hb+1
    const int wm   = (w & 3) * 32;      // warp row offset
    const int wn   = (w >> 2) * 32;     // warp col offset (0 or 32)

    float acc[2][4][4];                 // [mf][nf][c0..c3]
#pragma unroll
    for (int a = 0; a < 2; a++)
#pragma unroll
        for (int b = 0; b < 4; b++)
#pragma unroll
            for (int c = 0; c < 4; c++) acc[a][b][c] = 0.f;

    // lane-constant ldmatrix addressing
    const uint32_t a_m  = (uint32_t)(wm + ((lane >> 3) & 1) * 8 + (lane & 7));
    const uint32_t a_k8 = (uint32_t)((lane >> 4) * 8);
    const uint32_t b_n  = (uint32_t)(wn + ((lane >> 4) & 1) * 8 + (lane & 7));
    const uint32_t b_k8 = (uint32_t)(((lane >> 3) & 1) * 8);

    // ---- stage chunk 0 into buffer 0
    {
        const int k0 = 0;
#pragma unroll
        for (int j = 0; j < 4; j++) {
            int idx = t + 256 * j;
            int row = idx >> 3, kq = idx & 7;
            float4 v = *(const float4*)(x + (size_t)(row0 + row) * INF + k0 + kq * 4);
            __nv_bfloat16 h0 = __float2bfloat16(v.x), h1 = __float2bfloat16(v.y);
            __nv_bfloat16 h2 = __float2bfloat16(v.z), h3 = __float2bfloat16(v.w);
            uint2 hp, lp;
            hp.x = pack2(__bfloat162float(h0), __bfloat162float(h1));
            hp.y = pack2(__bfloat162float(h2), __bfloat162float(h3));
            lp.x = pack2(v.x - __bfloat162float(h0), v.y - __bfloat162float(h1));
            lp.y = pack2(v.z - __bfloat162float(h2), v.w - __bfloat162float(h3));
            *(uint2*)(sm + SM_AHI + row * PITCH + kq * 8) = hp;
            *(uint2*)(sm + SM_ALO + row * PITCH + kq * 8) = lp;
        }
#pragma unroll
        for (int j = 0; j < 8; j++) {
            int idx = t + 256 * j;
            int n = idx & 63, k = idx >> 6;
            int h = hb + (n >> 5), f = n & 31;
            float v = W[((size_t)h * INF + k0 + k) * OUTF + f];
            __nv_bfloat16 hh = __float2bfloat16(v);
            float hf = __bfloat162float(hh);
            __nv_bfloat16 ll = __float2bfloat16(v - hf);
            *(unsigned short*)(sm + SM_BHI + n * PITCH + k * 2) = __bfloat16_as_ushort(hh);
            *(unsigned short*)(sm + SM_BLO + n * PITCH + k * 2) = __bfloat16_as_ushort(ll);
        }
    }
    __syncthreads();

#pragma unroll 1
    for (int c = 0; c < 8; c++) {
        const uint32_t cb = (uint32_t)(c & 1) * BUF_SZ;       // compute buffer
        const uint32_t nb = (uint32_t)((c + 1) & 1) * BUF_SZ; // next (stage) buffer

        // 1) issue next chunk's global loads (latency hidden under MMA below)
        float4 xr[4];
        float  wv[8];
        if (c < 7) {
            const int k0 = (c + 1) * 32;
#pragma unroll
            for (int j = 0; j < 4; j++) {
                int idx = t + 256 * j;
                xr[j] = *(const float4*)(x + (size_t)(row0 + (idx >> 3)) * INF + k0 + (idx & 7) * 4);
            }
#pragma unroll
            for (int j = 0; j < 8; j++) {
                int idx = t + 256 * j;
                int n = idx & 63, k = idx >> 6;
                int h = hb + (n >> 5), f = n & 31;
                wv[j] = W[((size_t)h * INF + k0 + k) * OUTF + f];
            }
        }

        // 2) MMA on current buffer
#pragma unroll
        for (int ks = 0; ks < 32; ks += 16) {
            uint32_t ah[2][4], al[2][4], bh[4][2], bl[4][2];
#pragma unroll
            for (int mf = 0; mf < 2; mf++) {
                uint32_t addr = base + cb + SM_AHI + (a_m + mf * 16) * PITCH + (ks + a_k8) * 2;
                LDSM4(ah[mf][0], ah[mf][1], ah[mf][2], ah[mf][3], addr);
                LDSM4(al[mf][0], al[mf][1], al[mf][2], al[mf][3], addr + (SM_ALO - SM_AHI));
            }
#pragma unroll
            for (int np = 0; np < 2; np++) {
                uint32_t addr = base + cb + SM_BHI + (b_n + np * 16) * PITCH + (ks + b_k8) * 2;
                uint32_t r0, r1, r2, r3;
                LDSM4(r0, r1, r2, r3, addr);
                bh[np * 2][0] = r0; bh[np * 2][1] = r1;
                bh[np * 2 + 1][0] = r2; bh[np * 2 + 1][1] = r3;
                LDSM4(r0, r1, r2, r3, addr + (SM_BLO - SM_BHI));
                bl[np * 2][0] = r0; bl[np * 2][1] = r1;
                bl[np * 2 + 1][0] = r2; bl[np * 2 + 1][1] = r3;
            }
#pragma unroll
            for (int mf = 0; mf < 2; mf++)
#pragma unroll
                for (int nf = 0; nf < 4; nf++) {
                    MMA_BF16(acc[mf][nf], ah[mf], bh[nf][0], bh[nf][1]);
                    MMA_BF16(acc[mf][nf], ah[mf], bl[nf][0], bl[nf][1]);
                    MMA_BF16(acc[mf][nf], al[mf], bh[nf][0], bh[nf][1]);
                }
        }

        // 3) convert + store next chunk into the other buffer
        if (c < 7) {
#pragma unroll
            for (int j = 0; j < 4; j++) {
                int idx = t + 256 * j;
                int row = idx >> 3, kq = idx & 7;
                float4 v = xr[j];
                __nv_bfloat16 h0 = __float2bfloat16(v.x), h1 = __float2bfloat16(v.y);
                __nv_bfloat16 h2 = __float2bfloat16(v.z), h3 = __float2bfloat16(v.w);
                uint2 hp, lp;
                hp.x = pack2(__bfloat162float(h0), __bfloat162float(h1));
                hp.y = pack2(__bfloat162float(h2), __bfloat162float(h3));
                lp.x = pack2(v.x - __bfloat162float(h0), v.y - __bfloat162float(h1));
                lp.y = pack2(v.z - __bfloat162float(h2), v.w - __bfloat162float(h3));
                *(uint2*)(sm + nb + SM_AHI + row * PITCH + kq * 8) = hp;
                *(uint2*)(sm + nb + SM_ALO + row * PITCH + kq * 8) = lp;
            }
#pragma unroll
            for (int j = 0; j < 8; j++) {
                int idx = t + 256 * j;
                int n = idx & 63, k = idx >> 6;
                float v = wv[j];
                __nv_bfloat16 hh = __float2bfloat16(v);
                float hf = __bfloat162float(hh);
                __nv_bfloat16 ll = __float2bfloat16(v - hf);
                *(unsigned short*)(sm + nb + SM_BHI + n * PITCH + k * 2) = __bfloat16_as_ushort(hh);
                *(unsigned short*)(sm + nb + SM_BLO + n * PITCH + k * 2) = __bfloat16_as_ushort(ll);
            }
        }
        __syncthreads();
    }

    // epilogue: store Wh + fused logits (one head per warp)
    const int h  = hb + (w >> 2);
    const int g  = lane >> 2;
    const int tg = lane & 3;
    float asv[4][2], adv[4][2];
#pragma unroll
    for (int nf = 0; nf < 4; nf++) {
        asv[nf][0] = a_src[h * OUTF + nf * 8 + tg * 2];
        asv[nf][1] = a_src[h * OUTF + nf * 8 + tg * 2 + 1];
        adv[nf][0] = a_dst[h * OUTF + nf * 8 + tg * 2];
        adv[nf][1] = a_dst[h * OUTF + nf * 8 + tg * 2 + 1];
    }
#pragma unroll
    for (int mf = 0; mf < 2; mf++) {
        const int mrow = row0 + wm + mf * 16;
        float s0 = 0.f, d0 = 0.f, s1 = 0.f, d1 = 0.f;
#pragma unroll
        for (int nf = 0; nf < 4; nf++) {
            float c0 = acc[mf][nf][0], c1 = acc[mf][nf][1];
            float c2 = acc[mf][nf][2], c3 = acc[mf][nf][3];
            const int f = nf * 8 + tg * 2;
            float2 vlo; vlo.x = c0; vlo.y = c1;
            float2 vhi; vhi.x = c2; vhi.y = c3;
            *(float2*)(g_Wh + ((size_t)(h << 12) + mrow + g) * OUTF + f)     = vlo;
            *(float2*)(g_Wh + ((size_t)(h << 12) + mrow + 8 + g) * OUTF + f) = vhi;
            s0 += c0 * asv[nf][0] + c1 * asv[nf][1];
            d0 += c0 * adv[nf][0] + c1 * adv[nf][1];
            s1 += c2 * asv[nf][0] + c3 * asv[nf][1];
            d1 += c2 * adv[nf][0] + c3 * adv[nf][1];
        }
#pragma unroll
        for (int o = 1; o < 4; o <<= 1) {
            s0 += __shfl_xor_sync(0xffffffffu, s0, o);
            d0 += __shfl_xor_sync(0xffffffffu, d0, o);
            s1 += __shfl_xor_sync(0xffffffffu, s1, o);
            d1 += __shfl_xor_sync(0xffffffffu, d1, o);
        }
        if (tg == 0) {
            g_esrc[(h << 12) + mrow + g]     = s0;
            g_edst[(h << 12) + mrow + g]     = d0;
            g_esrc[(h << 12) + mrow + 8 + g] = s1;
            g_edst[(h << 12) + mrow + 8 + g] = d1;
        }
    }
}

__device__ __forceinline__ unsigned nib4(unsigned m) {
    return (((m & 0x01010101u) * 0x01020408u) >> 24) & 0xFu;
}

// ---------------------------------------------------------------------------
// scan: 1024 blocks x 128 thr, warp per row, prefetched stream (reads g_kind).
// ---------------------------------------------------------------------------
__global__ void __launch_bounds__(128) scan_kernel(const void* __restrict__ adjv) {
    const int t    = threadIdx.x;
    const int lane = t & 31;
    const int w    = t >> 5;
    const int r    = blockIdx.x * 4 + w;
    const int kind = g_kind;

    int base = 0;
    if (kind == 0) {
        const uint4* rp = (const uint4*)((const unsigned char*)adjv + (size_t)r * NNODE);
        uint4 cur = rp[lane];
        for (int it = 0; it < 8; it++) {
            uint4 nxt;
            if (it < 7) nxt = rp[(it + 1) * 32 + lane];
            unsigned m16 =  nib4(__vcmpne4(cur.x, 0u))
                         | (nib4(__vcmpne4(cur.y, 0u)) << 4)
                         | (nib4(__vcmpne4(cur.z, 0u)) << 8)
                         | (nib4(__vcmpne4(cur.w, 0u)) << 12);
            const int c0 = (it << 9) + (lane << 4);
            if ((unsigned)(r - c0) < 16u) m16 |= 1u << (r - c0);
            int cnt = __popc(m16), incl = cnt;
#pragma unroll
            for (int o = 1; o < 32; o <<= 1) {
                int v = __shfl_up_sync(0xffffffffu, incl, o);
                if (lane >= o) incl += v;
            }
            int pos = base + (incl - cnt);
            int tot = __shfl_sync(0xffffffffu, incl, 31);
            while (m16) {
                int bi = __ffs(m16) - 1;
                m16 &= m16 - 1;
                if (pos < DEGCAP) g_adjn[r][pos] = (unsigned short)(c0 + bi);
                pos++;
            }
            base += tot;
            cur = nxt;
        }
    } else {
        const uint4* rp = (const uint4*)((const unsigned char*)adjv + ((size_t)r * NNODE << 2));
        uint4 cur[4];
#pragma unroll
        for (int q = 0; q < 4; q++) cur[q] = rp[lane * 4 + q];
        for (int it = 0; it < 8; it++) {
            uint4 nxt[4];
            if (it < 7) {
#pragma unroll
                for (int q = 0; q < 4; q++)
                    nxt[q] = rp[(it + 1) * 128 + lane * 4 + q];
            }
            unsigned m16 = 0;
#pragma unroll
            for (int q = 0; q < 4; q++) {
                m16 |= (unsigned)(cur[q].x != 0) << (q * 4 + 0);
                m16 |= (unsigned)(cur[q].y != 0) << (q * 4 + 1);
                m16 |= (unsigned)(cur[q].z != 0) << (q * 4 + 2);
                m16 |= (unsigned)(cur[q].w != 0) << (q * 4 + 3);
            }
            const int c0 = (it << 9) + (lane << 4);
            if ((unsigned)(r - c0) < 16u) m16 |= 1u << (r - c0);
            int cnt = __popc(m16), incl = cnt;
#pragma unroll
            for (int o = 1; o < 32; o <<= 1) {
                int v = __shfl_up_sync(0xffffffffu, incl, o);
                if (lane >= o) incl += v;
            }
            int pos = base + (incl - cnt);
            int tot = __shfl_sync(0xffffffffu, incl, 31);
            while (m16) {
                int bi = __ffs(m16) - 1;
                m16 &= m16 - 1;
                if (pos < DEGCAP) g_adjn[r][pos] = (unsigned short)(c0 + bi);
                pos++;
            }
            base += tot;
#pragma unroll
            for (int q = 0; q < 4; q++) cur[q] = nxt[q];
        }
    }
    if (lane == 31) g_deg[r] = (base > DEGCAP) ? DEGCAP : base;
}

// ---------------------------------------------------------------------------
// agg: warp per (node, head); edge-parallel alpha, shfl-broadcast gather.
// ---------------------------------------------------------------------------
__global__ void __launch_bounds__(256) agg_kernel(
    const float* __restrict__ bias, float* __restrict__ out) {
    const int i    = blockIdx.x;
    const int t    = threadIdx.x;
    const int w    = t >> 5;
    const int lane = t & 31;

    const int    deg = g_deg[i];
    const float  es  = g_esrc[(w << 12) + i];
    const float* ed  = g_edst + (w << 12);
    const float* whb = g_Wh + (((size_t)w << 12) * OUTF) + lane;

    float acc = 0.f, ssum = 0.f;
    for (int c0 = 0; c0 < deg; c0 += 32) {
        const int k = c0 + lane;
        int   j = 0;
        float p = 0.f;
        if (k < deg) {
            j = (int)g_adjn[i][k];
            float e = es + __ldg(&ed[j]);
            e = (e >= 0.f) ? e : NEG_SLOPE * e;
            p = __expf(e);
        }
        ssum += p;
        const int m = (deg - c0 < 32) ? (deg - c0) : 32;
        int kk = 0;
        for (; kk + 2 <= m; kk += 2) {
            int   ja = __shfl_sync(0xffffffffu, j, kk);
            float pa = __shfl_sync(0xffffffffu, p, kk);
            int   jb = __shfl_sync(0xffffffffu, j, kk + 1);
            float pb = __shfl_sync(0xffffffffu, p, kk + 1);
            float wa = whb[(size_t)ja * OUTF];
            float wb = whb[(size_t)jb * OUTF];
            acc = fmaf(pa, wa, acc);
            acc = fmaf(pb, wb, acc);
        }
        if (kk < m) {
            int   ja = __shfl_sync(0xffffffffu, j, kk);
            float pa = __shfl_sync(0xffffffffu, p, kk);
            acc = fmaf(pa, whb[(size_t)ja * OUTF], acc);
        }
    }
#pragma unroll
    for (int o = 16; o; o >>= 1)
        ssum += __shfl_xor_sync(0xffffffffu, ssum, o);

    out[(size_t)i * (NH * OUTF) + w * OUTF + lane] = acc / ssum + bias[w * OUTF + lane];
}

// ---------------------------------------------------------------------------
extern "C" void kernel_launch(void* const* d_in, const int* in_sizes, int n_in,
                              void* d_out, int out_size) {
    const float* x     = (const float*)d_in[0];
    const void*  adj   = d_in[1];
    const float* W     = (const float*)d_in[2];
    const float* a_src = (const float*)d_in[3];
    const float* a_dst = (const float*)d_in[4];
    const float* bias  = (const float*)d_in[5];
    float*       out   = (float*)d_out;

    cudaFuncSetAttribute(gemm_tc_kernel,
                         cudaFuncAttributeMaxDynamicSharedMemorySize, DSMEM_BYTES);
    gemm_tc_kernel<<<128, 256, DSMEM_BYTES>>>(x, W, a_src, a_dst, adj);  // writes g_kind
    scan_kernel<<<NNODE / 4, 128>>>(adj);                                // reads g_kind
    agg_kernel<<<NNODE, 256>>>(bias, out);
}